// round 7
// baseline (speedup 1.0000x reference)
#include <cuda_runtime.h>
#include <cuda_fp16.h>
#include <math.h>
#include <stdint.h>

#define BB 64
#define TT 2048
#define DD 512
#define UU 512

// ---------------- device scratch ----------------
__device__ float g_comb[BB * UU];
__device__ float g_scores[BB * TT];
__device__ float g_spart[2 * BB * TT];
__device__ float g_stats[BB * 2];
__device__ float g_partial[BB * 32 * 4 * DD];
// B fragments (fp16, 2 n8 per uint4): [n4 0..31][k16 0..31][lane 0..31]
__device__ uint4 g_bfrag[32 * 32 * 32];

// ---------------- helpers ----------------
__device__ __forceinline__ uint32_t smem_u32(const void* p) {
    uint32_t a;
    asm("{ .reg .u64 t; cvta.to.shared.u64 t, %1; cvt.u32.u64 %0, t; }" : "=r"(a) : "l"(p));
    return a;
}
__device__ __forceinline__ void cpa16(uint32_t dst, const void* src) {
    asm volatile("cp.async.cg.shared.global [%0], [%1], 16;" :: "r"(dst), "l"(src) : "memory");
}
#define CP_COMMIT() asm volatile("cp.async.commit_group;" ::: "memory")
#define CP_WAIT(n)  asm volatile("cp.async.wait_group %0;" :: "n"(n) : "memory")

__device__ __forceinline__ uint32_t pack_h2(float x, float y) {
    __half2 h = __floats2half2_rn(x, y);
    return *(uint32_t*)&h;
}

__device__ __forceinline__ void mma_f16(float* d, const uint4& a, uint32_t b0, uint32_t b1) {
    asm volatile(
        "mma.sync.aligned.m16n8k16.row.col.f32.f16.f16.f32 "
        "{%0,%1,%2,%3}, {%4,%5,%6,%7}, {%8,%9}, {%0,%1,%2,%3};"
        : "+f"(d[0]), "+f"(d[1]), "+f"(d[2]), "+f"(d[3])
        : "r"(a.x), "r"(a.y), "r"(a.z), "r"(a.w), "r"(b0), "r"(b1));
}

// ---------------- prep: W1 -> fp16 fragment-major (2 n8 per uint4) ----------------
__global__ void prep_bfrag_kernel(const float* __restrict__ W1) {
    int gidx = blockIdx.x * 256 + threadIdx.x;      // 32768
    int lane = gidx & 31;
    int k16 = (gidx >> 5) & 31;
    int n4 = gidx >> 10;
    int g = lane >> 2, tg = lane & 3;
    int k = k16 * 16 + 2 * tg;
    int ua = (2 * n4) * 8 + g;
    int ub = (2 * n4 + 1) * 8 + g;
    uint4 o;
    o.x = pack_h2(W1[(size_t)k * UU + ua],       W1[(size_t)(k + 1) * UU + ua]);
    o.y = pack_h2(W1[(size_t)(k + 8) * UU + ua], W1[(size_t)(k + 9) * UU + ua]);
    o.z = pack_h2(W1[(size_t)k * UU + ub],       W1[(size_t)(k + 1) * UU + ub]);
    o.w = pack_h2(W1[(size_t)(k + 8) * UU + ub], W1[(size_t)(k + 9) * UU + ub]);
    g_bfrag[gidx] = o;
}

// ---------------- comb[b][u] ----------------
__global__ void comb_kernel(const float* __restrict__ hidden,
                            const float* __restrict__ W2,
                            const float* __restrict__ W1b,
                            const float* __restrict__ W2b) {
    int b = blockIdx.x;
    int u = threadIdx.x;
    __shared__ float h[DD];
    h[u] = hidden[b * DD + u];
    __syncthreads();
    float acc = W1b[u] + W2b[u];
#pragma unroll 8
    for (int d = 0; d < DD; ++d)
        acc = fmaf(h[d], W2[d * UU + u], acc);
    g_comb[b * UU + u] = acc;
}

// ---------------- score GEMM: cp.async A staging + in-loop fp16 convert ----------------
// grid (2 nchunk, 16 ttile, 64 b), 512 threads = 16 warps (4 warpM x 4 warpN)
// A: fp32 tile 128x16 per k16, triple-buffered SMEM (pitch 20 floats), distance-2 prefetch.
// B: fragment-major LDG.128 from g_bfrag, register double-buffer (unchanged from R5).
#define APITCH 20
#define ABUF   (128 * APITCH)

__global__ void __launch_bounds__(512)
score_kernel(const float* __restrict__ feat, const float* __restrict__ Vw) {
    __shared__ __align__(16) float As[3][ABUF];
    __shared__ float comb_s[256];
    __shared__ float v_s[256];
    __shared__ float srow[128];

    uint32_t asb = smem_u32(As);
    int tid = threadIdx.x;
    int wid = tid >> 5, lane = tid & 31;
    int warpM = wid & 3, warpN = wid >> 2;
    int g = lane >> 2, tg = lane & 3;

    int nchunk = blockIdx.x;
    int t0 = blockIdx.y << 7;
    int b = blockIdx.z;
    int u0 = nchunk << 8;

    if (tid < 256) {
        comb_s[tid] = g_comb[b * UU + u0 + tid];
        v_s[tid] = Vw[u0 + tid];
    }
    if (tid < 128) srow[tid] = 0.f;

    const float* fbase = feat + ((size_t)b * TT + t0) * DD;
    const uint4* pB = g_bfrag + (((size_t)(nchunk * 16 + warpN * 4) * 32) * 32 + lane);

    // one 16B cp.async per thread per k16: row = tid>>2, seg = tid&3
    int frow = tid >> 2, fseg = tid & 3;
    const float* fsrc = fbase + (size_t)frow * DD + fseg * 4;
    uint32_t fdst = asb + (frow * APITCH + fseg * 4) * 4;

    auto fillA = [&](int c, int buf) {
        cpa16(fdst + buf * (ABUF * 4), fsrc + c * 16);
    };

    // fragment conversion from SMEM buffer
    int rb0 = warpM * 32 + g;              // mt=0 base row
    auto ldcvt = [&](int buf, int mt) -> uint4 {
        const float* sp = As[buf] + (rb0 + mt * 16) * APITCH + 2 * tg;
        float2 f00 = *(const float2*)(sp);
        float2 f10 = *(const float2*)(sp + 8 * APITCH);
        float2 f01 = *(const float2*)(sp + 8);
        float2 f11 = *(const float2*)(sp + 8 * APITCH + 8);
        uint4 o;
        o.x = pack_h2(f00.x, f00.y);
        o.y = pack_h2(f10.x, f10.y);
        o.z = pack_h2(f01.x, f01.y);
        o.w = pack_h2(f11.x, f11.y);
        return o;
    };

    float acc[2][8][4];
#pragma unroll
    for (int i = 0; i < 2; ++i)
#pragma unroll
        for (int j = 0; j < 8; ++j)
#pragma unroll
            for (int q = 0; q < 4; ++q) acc[i][j][q] = 0.f;

    fillA(0, 0); CP_COMMIT();
    fillA(1, 1); CP_COMMIT();

    uint4 Bb[2][4];
#pragma unroll
    for (int j = 0; j < 4; ++j) Bb[0][j] = pB[j * 1024];

#pragma unroll 1
    for (int k16 = 0; k16 < 32; ++k16) {
        int buf = k16 % 3;
        CP_WAIT(1);
        __syncthreads();
        uint4 A0 = ldcvt(buf, 0);
        uint4 A1 = ldcvt(buf, 1);
        // refill (safe: target buf last read at iter k16-1, ordered by this iter's barrier)
        if (k16 < 30) fillA(k16 + 2, (k16 + 2) % 3);
        CP_COMMIT();   // always commit (possibly empty) to keep group accounting uniform

        int cur = k16 & 1, nxt = cur ^ 1;
        if (k16 < 31) {
            int boff = (k16 + 1) * 32;
#pragma unroll
            for (int j = 0; j < 4; ++j) Bb[nxt][j] = pB[j * 1024 + boff];
        }
#pragma unroll
        for (int n4 = 0; n4 < 4; ++n4) {
            uint4 B4 = Bb[cur][n4];
            mma_f16(acc[0][2 * n4],     A0, B4.x, B4.y);
            mma_f16(acc[0][2 * n4 + 1], A0, B4.z, B4.w);
            mma_f16(acc[1][2 * n4],     A1, B4.x, B4.y);
            mma_f16(acc[1][2 * n4 + 1], A1, B4.z, B4.w);
        }
    }

    __syncthreads();

    // ---- epilogue: s = sum_u v[u] * tanh(acc + comb[u]) ----
    float s[4] = {0.f, 0.f, 0.f, 0.f};
#pragma unroll
    for (int nt = 0; nt < 8; ++nt) {
#pragma unroll
        for (int j = 0; j < 2; ++j) {
            int ul = warpN * 64 + nt * 8 + 2 * tg + j;
            float cb = comb_s[ul], vv = v_s[ul];
            s[0] = fmaf(vv, tanhf(acc[0][nt][j] + cb), s[0]);
            s[1] = fmaf(vv, tanhf(acc[0][nt][2 + j] + cb), s[1]);
            s[2] = fmaf(vv, tanhf(acc[1][nt][j] + cb), s[2]);
            s[3] = fmaf(vv, tanhf(acc[1][nt][2 + j] + cb), s[3]);
        }
    }
#pragma unroll
    for (int i = 0; i < 4; ++i) {
        s[i] += __shfl_xor_sync(0xffffffffu, s[i], 1);
        s[i] += __shfl_xor_sync(0xffffffffu, s[i], 2);
    }
    if (tg == 0) {
        int rbase = warpM * 32;
        atomicAdd(&srow[rbase + g], s[0]);
        atomicAdd(&srow[rbase + g + 8], s[1]);
        atomicAdd(&srow[rbase + 16 + g], s[2]);
        atomicAdd(&srow[rbase + 16 + g + 8], s[3]);
    }
    __syncthreads();
    if (tid < 128)
        g_spart[(size_t)nchunk * BB * TT + b * TT + t0 + tid] = srow[tid];
}

// ---------------- softmax stats + score combine ----------------
__global__ void stats_kernel() {
    int b = blockIdx.x;
    int tid = threadIdx.x;   // 256
    __shared__ float red[256];
    float m = -INFINITY;
    for (int t = tid; t < TT; t += 256) {
        float sc = g_spart[b * TT + t] + g_spart[BB * TT + b * TT + t];
        g_scores[b * TT + t] = sc;
        m = fmaxf(m, sc);
    }
    red[tid] = m;
    __syncthreads();
    for (int s = 128; s > 0; s >>= 1) {
        if (tid < s) red[tid] = fmaxf(red[tid], red[tid + s]);
        __syncthreads();
    }
    float mx = red[0];
    __syncthreads();
    float sm = 0.f;
    for (int t = tid; t < TT; t += 256)
        sm += expf(g_scores[b * TT + t] - mx);
    red[tid] = sm;
    __syncthreads();
    for (int s = 128; s > 0; s >>= 1) {
        if (tid < s) red[tid] += red[tid + s];
        __syncthreads();
    }
    if (tid == 0) { g_stats[b * 2] = mx; g_stats[b * 2 + 1] = red[0]; }
}

// ---------------- context partials: 32 splits of 64 t ----------------
__global__ void __launch_bounds__(512)
ctx_partial_kernel(const float* __restrict__ feat) {
    int b = blockIdx.x;
    int s = blockIdx.y;              // 0..31
    int tid = threadIdx.x;           // 512
    __shared__ float w[64];
    float mx = g_stats[b * 2], inv = 1.0f / g_stats[b * 2 + 1];
    int t0 = s * 64;
    if (tid < 64)
        w[tid] = expf(g_scores[b * TT + t0 + tid] - mx) * inv;
    __syncthreads();
    int tl = tid >> 7;               // 0..3
    int dq = (tid & 127) << 2;
    float4 acc = make_float4(0.f, 0.f, 0.f, 0.f);
    const float* fb = feat + ((size_t)b * TT + t0) * DD;
#pragma unroll 4
    for (int i = 0; i < 16; ++i) {
        int t = tl + (i << 2);
        float4 f = *(const float4*)(fb + (size_t)t * DD + dq);
        float ww = w[t];
        acc.x = fmaf(ww, f.x, acc.x);
        acc.y = fmaf(ww, f.y, acc.y);
        acc.z = fmaf(ww, f.z, acc.z);
        acc.w = fmaf(ww, f.w, acc.w);
    }
    *(float4*)(&g_partial[((((size_t)b * 32 + s) * 4) + tl) * DD + dq]) = acc;
}

__global__ void ctx_reduce_kernel(float* __restrict__ out) {
    int b = blockIdx.x;
    int d = threadIdx.x;
    float a = 0.f;
#pragma unroll
    for (int s = 0; s < 128; ++s)
        a += g_partial[((size_t)b * 128 + s) * DD + d];
    out[b * DD + d] = a;
}

// ---------------- launch ----------------
extern "C" void kernel_launch(void* const* d_in, const int* in_sizes, int n_in,
                              void* d_out, int out_size) {
    const float* features = (const float*)d_in[0];
    const float* hidden   = (const float*)d_in[1];
    const float* W1_w     = (const float*)d_in[2];
    const float* W1_b     = (const float*)d_in[3];
    const float* W2_w     = (const float*)d_in[4];
    const float* W2_b     = (const float*)d_in[5];
    const float* V_w      = (const float*)d_in[6];
    // V_b: constant shift, softmax-invariant -> dropped
    float* out = (float*)d_out;

    prep_bfrag_kernel<<<32 * 32 * 32 / 256, 256>>>(W1_w);
    comb_kernel<<<BB, UU>>>(hidden, W2_w, W1_b, W2_b);

    dim3 sgrid(2, 16, BB);
    score_kernel<<<sgrid, 512>>>(features, V_w);

    stats_kernel<<<BB, 256>>>();
    dim3 cgrid(BB, 32);
    ctx_partial_kernel<<<cgrid, 512>>>(features);
    ctx_reduce_kernel<<<BB, DD>>>(out);
}

// round 8
// speedup vs baseline: 1.9984x; 1.9984x over previous
#include <cuda_runtime.h>
#include <cuda_fp16.h>
#include <math.h>
#include <stdint.h>

#define BB 64
#define TT 2048
#define DD 512
#define UU 512

// ---------------- device scratch ----------------
__device__ float g_comb[BB * UU];
__device__ float g_scores[BB * TT];
__device__ float g_spart[2 * BB * TT];
__device__ float g_stats[BB * 2];
__device__ float g_pmax[BB * 8];
__device__ float g_psum[BB * 8];
__device__ float g_partial[BB * 32 * 4 * DD];
// A fragments: [b][t16 0..127][k16 0..31][lane 0..31] -> uint4 (a0,a1,a2,a3) fp16x2
__device__ uint4 g_afrag[BB * 128 * 32 * 32];
// B fragments (fp16, 2 n8 per uint4): [n4 0..31][k16 0..31][lane 0..31]
__device__ uint4 g_bfrag[32 * 32 * 32];

// ---------------- helpers ----------------
__device__ __forceinline__ uint32_t pack_h2(float x, float y) {
    __half2 h = __floats2half2_rn(x, y);
    return *(uint32_t*)&h;
}

__device__ __forceinline__ void mma_f16(float* d, const uint4& a, uint32_t b0, uint32_t b1) {
    asm volatile(
        "mma.sync.aligned.m16n8k16.row.col.f32.f16.f16.f32 "
        "{%0,%1,%2,%3}, {%4,%5,%6,%7}, {%8,%9}, {%0,%1,%2,%3};"
        : "+f"(d[0]), "+f"(d[1]), "+f"(d[2]), "+f"(d[3])
        : "r"(a.x), "r"(a.y), "r"(a.z), "r"(a.w), "r"(b0), "r"(b1));
}

// ---------------- prep: features fp32 -> fp16 fragment-major ----------------
__global__ void prep_afrag_kernel(const float* __restrict__ feat) {
    int gidx = blockIdx.x * 256 + threadIdx.x;      // 8388608
    int lane = gidx & 31;
    int k16 = (gidx >> 5) & 31;
    int t16 = (gidx >> 10) & 127;
    int b = gidx >> 17;
    int g = lane >> 2, tg = lane & 3;
    int tA = t16 * 16 + g;
    int kA = k16 * 16 + 2 * tg;
    const float* base = feat + ((size_t)b * TT) * DD;
    float2 f00 = *(const float2*)(base + (size_t)tA * DD + kA);
    float2 f10 = *(const float2*)(base + (size_t)(tA + 8) * DD + kA);
    float2 f01 = *(const float2*)(base + (size_t)tA * DD + kA + 8);
    float2 f11 = *(const float2*)(base + (size_t)(tA + 8) * DD + kA + 8);
    uint4 o;
    o.x = pack_h2(f00.x, f00.y);
    o.y = pack_h2(f10.x, f10.y);
    o.z = pack_h2(f01.x, f01.y);
    o.w = pack_h2(f11.x, f11.y);
    g_afrag[gidx] = o;
}

// ---------------- prep: W1 -> fp16 fragment-major (2 n8 per uint4) ----------------
__global__ void prep_bfrag_kernel(const float* __restrict__ W1) {
    int gidx = blockIdx.x * 256 + threadIdx.x;      // 32768
    int lane = gidx & 31;
    int k16 = (gidx >> 5) & 31;
    int n4 = gidx >> 10;
    int g = lane >> 2, tg = lane & 3;
    int k = k16 * 16 + 2 * tg;
    int ua = (2 * n4) * 8 + g;
    int ub = (2 * n4 + 1) * 8 + g;
    uint4 o;
    o.x = pack_h2(W1[(size_t)k * UU + ua],       W1[(size_t)(k + 1) * UU + ua]);
    o.y = pack_h2(W1[(size_t)(k + 8) * UU + ua], W1[(size_t)(k + 9) * UU + ua]);
    o.z = pack_h2(W1[(size_t)k * UU + ub],       W1[(size_t)(k + 1) * UU + ub]);
    o.w = pack_h2(W1[(size_t)(k + 8) * UU + ub], W1[(size_t)(k + 9) * UU + ub]);
    g_bfrag[gidx] = o;
}

// ---------------- comb: tiled (8 b x 128 u per CTA), hidden in SMEM ----------------
__global__ void __launch_bounds__(128)
comb_kernel(const float* __restrict__ hidden,
            const float* __restrict__ W2,
            const float* __restrict__ W1b,
            const float* __restrict__ W2b) {
    int uc = blockIdx.x & 3;
    int bg = blockIdx.x >> 2;     // 0..7
    int tid = threadIdx.x;        // 128
    int u = uc * 128 + tid;
    __shared__ float h[8][DD];
    for (int i = tid; i < 8 * DD; i += 128)
        h[i >> 9][i & (DD - 1)] = hidden[(bg * 8 + (i >> 9)) * DD + (i & (DD - 1))];
    __syncthreads();
    float base = W1b[u] + W2b[u];
    float acc[8];
#pragma unroll
    for (int i = 0; i < 8; ++i) acc[i] = base;
#pragma unroll 4
    for (int d = 0; d < DD; ++d) {
        float w = W2[(size_t)d * UU + u];
#pragma unroll
        for (int i = 0; i < 8; ++i)
            acc[i] = fmaf(h[i][d], w, acc[i]);
    }
#pragma unroll
    for (int i = 0; i < 8; ++i)
        g_comb[(bg * 8 + i) * UU + u] = acc[i];
}

// ---------------- score GEMM: round-5 winner (unchanged) ----------------
// grid (2 nchunk, 16 ttile, 64 b), 512 threads = 16 warps (4 warpM x 4 warpN)
__global__ void __launch_bounds__(512)
score_kernel(const float* __restrict__ Vw) {
    __shared__ float comb_s[256];
    __shared__ float v_s[256];
    __shared__ float srow[128];

    int tid = threadIdx.x;
    int wid = tid >> 5, lane = tid & 31;
    int warpM = wid & 3, warpN = wid >> 2;
    int g = lane >> 2, tg = lane & 3;

    int nchunk = blockIdx.x;
    int t0 = blockIdx.y << 7;
    int b = blockIdx.z;
    int u0 = nchunk << 8;

    if (tid < 256) {
        comb_s[tid] = g_comb[b * UU + u0 + tid];
        v_s[tid] = Vw[u0 + tid];
    }
    if (tid < 128) srow[tid] = 0.f;

    int tt0 = (t0 >> 4) + warpM * 2;
    const uint4* pA0 = g_afrag + (((size_t)(b * 128 + tt0) * 32) * 32 + lane);
    const uint4* pA1 = pA0 + 32 * 32;
    const uint4* pB  = g_bfrag + (((size_t)(nchunk * 16 + warpN * 4) * 32) * 32 + lane);

    float acc[2][8][4];
#pragma unroll
    for (int i = 0; i < 2; ++i)
#pragma unroll
        for (int j = 0; j < 8; ++j)
#pragma unroll
            for (int q = 0; q < 4; ++q) acc[i][j][q] = 0.f;

    uint4 Ab[2][2], Bb[2][4];
    Ab[0][0] = pA0[0];
    Ab[0][1] = pA1[0];
#pragma unroll
    for (int j = 0; j < 4; ++j) Bb[0][j] = pB[j * 1024];

#pragma unroll 2
    for (int k16 = 0; k16 < 32; ++k16) {
        int cur = k16 & 1, nxt = cur ^ 1;
        if (k16 < 31) {
            int off = (k16 + 1) * 32;
            Ab[nxt][0] = pA0[off];
            Ab[nxt][1] = pA1[off];
#pragma unroll
            for (int j = 0; j < 4; ++j) Bb[nxt][j] = pB[j * 1024 + off];
        }
#pragma unroll
        for (int n4 = 0; n4 < 4; ++n4) {
            uint4 B4 = Bb[cur][n4];
            mma_f16(acc[0][2 * n4],     Ab[cur][0], B4.x, B4.y);
            mma_f16(acc[0][2 * n4 + 1], Ab[cur][0], B4.z, B4.w);
            mma_f16(acc[1][2 * n4],     Ab[cur][1], B4.x, B4.y);
            mma_f16(acc[1][2 * n4 + 1], Ab[cur][1], B4.z, B4.w);
        }
    }

    __syncthreads();

    // ---- epilogue: s = sum_u v[u] * tanh(acc + comb[u]) ----
    float s[4] = {0.f, 0.f, 0.f, 0.f};
#pragma unroll
    for (int nt = 0; nt < 8; ++nt) {
#pragma unroll
        for (int j = 0; j < 2; ++j) {
            int ul = warpN * 64 + nt * 8 + 2 * tg + j;
            float cb = comb_s[ul], vv = v_s[ul];
            s[0] = fmaf(vv, tanhf(acc[0][nt][j] + cb), s[0]);
            s[1] = fmaf(vv, tanhf(acc[0][nt][2 + j] + cb), s[1]);
            s[2] = fmaf(vv, tanhf(acc[1][nt][j] + cb), s[2]);
            s[3] = fmaf(vv, tanhf(acc[1][nt][2 + j] + cb), s[3]);
        }
    }
#pragma unroll
    for (int i = 0; i < 4; ++i) {
        s[i] += __shfl_xor_sync(0xffffffffu, s[i], 1);
        s[i] += __shfl_xor_sync(0xffffffffu, s[i], 2);
    }
    if (tg == 0) {
        int rbase = warpM * 32;
        atomicAdd(&srow[rbase + g], s[0]);
        atomicAdd(&srow[rbase + g + 8], s[1]);
        atomicAdd(&srow[rbase + 16 + g], s[2]);
        atomicAdd(&srow[rbase + 16 + g + 8], s[3]);
    }
    __syncthreads();
    if (tid < 128)
        g_spart[(size_t)nchunk * BB * TT + b * TT + t0 + tid] = srow[tid];
}

// ---------------- stats phase A: per-256t combine + local max/sumexp ----------------
__global__ void __launch_bounds__(256)
stats_a_kernel() {
    int b = blockIdx.x;
    int seg = blockIdx.y;            // 0..7
    int tid = threadIdx.x;           // 256, one t each
    int t = seg * 256 + tid;
    __shared__ float red[256];

    float sc = g_spart[b * TT + t] + g_spart[BB * TT + b * TT + t];
    g_scores[b * TT + t] = sc;

    red[tid] = sc;
    __syncthreads();
    for (int s = 128; s > 0; s >>= 1) {
        if (tid < s) red[tid] = fmaxf(red[tid], red[tid + s]);
        __syncthreads();
    }
    float mx = red[0];
    __syncthreads();
    red[tid] = expf(sc - mx);
    __syncthreads();
    for (int s = 128; s > 0; s >>= 1) {
        if (tid < s) red[tid] += red[tid + s];
        __syncthreads();
    }
    if (tid == 0) {
        g_pmax[b * 8 + seg] = mx;
        g_psum[b * 8 + seg] = red[0];
    }
}

// ---------------- stats phase B: combine 8 partials ----------------
__global__ void __launch_bounds__(32)
stats_b_kernel() {
    int b = blockIdx.x;
    int tid = threadIdx.x;
    float m = (tid < 8) ? g_pmax[b * 8 + tid] : -INFINITY;
#pragma unroll
    for (int o = 4; o > 0; o >>= 1)
        m = fmaxf(m, __shfl_xor_sync(0xffffffffu, m, o));
    float sv = (tid < 8) ? g_psum[b * 8 + tid] * expf(g_pmax[b * 8 + tid] - m) : 0.f;
#pragma unroll
    for (int o = 4; o > 0; o >>= 1)
        sv += __shfl_xor_sync(0xffffffffu, sv, o);
    if (tid == 0) { g_stats[b * 2] = m; g_stats[b * 2 + 1] = sv; }
}

// ---------------- context partials: 32 splits of 64 t ----------------
__global__ void __launch_bounds__(512)
ctx_partial_kernel(const float* __restrict__ feat) {
    int b = blockIdx.x;
    int s = blockIdx.y;              // 0..31
    int tid = threadIdx.x;           // 512
    __shared__ float w[64];
    float mx = g_stats[b * 2], inv = 1.0f / g_stats[b * 2 + 1];
    int t0 = s * 64;
    if (tid < 64)
        w[tid] = expf(g_scores[b * TT + t0 + tid] - mx) * inv;
    __syncthreads();
    int tl = tid >> 7;               // 0..3
    int dq = (tid & 127) << 2;
    float4 acc = make_float4(0.f, 0.f, 0.f, 0.f);
    const float* fb = feat + ((size_t)b * TT + t0) * DD;
#pragma unroll 4
    for (int i = 0; i < 16; ++i) {
        int t = tl + (i << 2);
        float4 f = *(const float4*)(fb + (size_t)t * DD + dq);
        float ww = w[t];
        acc.x = fmaf(ww, f.x, acc.x);
        acc.y = fmaf(ww, f.y, acc.y);
        acc.z = fmaf(ww, f.z, acc.z);
        acc.w = fmaf(ww, f.w, acc.w);
    }
    *(float4*)(&g_partial[((((size_t)b * 32 + s) * 4) + tl) * DD + dq]) = acc;
}

__global__ void ctx_reduce_kernel(float* __restrict__ out) {
    int b = blockIdx.x;
    int d = threadIdx.x;
    float a = 0.f;
#pragma unroll
    for (int s = 0; s < 128; ++s)
        a += g_partial[((size_t)b * 128 + s) * DD + d];
    out[b * DD + d] = a;
}

// ---------------- launch ----------------
extern "C" void kernel_launch(void* const* d_in, const int* in_sizes, int n_in,
                              void* d_out, int out_size) {
    const float* features = (const float*)d_in[0];
    const float* hidden   = (const float*)d_in[1];
    const float* W1_w     = (const float*)d_in[2];
    const float* W1_b     = (const float*)d_in[3];
    const float* W2_w     = (const float*)d_in[4];
    const float* W2_b     = (const float*)d_in[5];
    const float* V_w      = (const float*)d_in[6];
    // V_b: constant shift, softmax-invariant -> dropped
    float* out = (float*)d_out;

    prep_afrag_kernel<<<BB * 128 * 32 * 32 / 256, 256>>>(features);
    prep_bfrag_kernel<<<32 * 32 * 32 / 256, 256>>>(W1_w);
    comb_kernel<<<32, 128>>>(hidden, W2_w, W1_b, W2_b);

    dim3 sgrid(2, 16, BB);
    score_kernel<<<sgrid, 512>>>(V_w);

    dim3 stgrid(BB, 8);
    stats_a_kernel<<<stgrid, 256>>>();
    stats_b_kernel<<<BB, 32>>>();

    dim3 cgrid(BB, 32);
    ctx_partial_kernel<<<cgrid, 512>>>(features);
    ctx_reduce_kernel<<<BB, DD>>>(out);
}

// round 9
// speedup vs baseline: 2.0306x; 1.0161x over previous
#include <cuda_runtime.h>
#include <cuda_fp16.h>
#include <math.h>
#include <stdint.h>

#define BB 64
#define TT 2048
#define DD 512
#define UU 512

// ---------------- device scratch ----------------
__device__ float g_comb[BB * UU];
__device__ float g_scores[BB * TT];
__device__ float g_spart[2 * BB * TT];
__device__ float g_stats[BB * 2];
__device__ float g_partial[BB * 64 * DD];
// A fragments: [b][t16 0..127][k16 0..31][lane 0..31] -> uint4 (a0,a1,a2,a3) fp16x2
__device__ uint4 g_afrag[BB * 128 * 32 * 32];
// B fragments (fp16, 2 n8 per uint4): [n4 0..31][k16 0..31][lane 0..31]
__device__ uint4 g_bfrag[32 * 32 * 32];

// ---------------- helpers ----------------
__device__ __forceinline__ uint32_t pack_h2(float x, float y) {
    __half2 h = __floats2half2_rn(x, y);
    return *(uint32_t*)&h;
}

__device__ __forceinline__ void mma_f16(float* d, const uint4& a, uint32_t b0, uint32_t b1) {
    asm volatile(
        "mma.sync.aligned.m16n8k16.row.col.f32.f16.f16.f32 "
        "{%0,%1,%2,%3}, {%4,%5,%6,%7}, {%8,%9}, {%0,%1,%2,%3};"
        : "+f"(d[0]), "+f"(d[1]), "+f"(d[2]), "+f"(d[3])
        : "r"(a.x), "r"(a.y), "r"(a.z), "r"(a.w), "r"(b0), "r"(b1));
}

// ---------------- prep: features fp32 -> fp16 fragment-major ----------------
__global__ void prep_afrag_kernel(const float* __restrict__ feat) {
    int gidx = blockIdx.x * 256 + threadIdx.x;      // 8388608
    int lane = gidx & 31;
    int k16 = (gidx >> 5) & 31;
    int t16 = (gidx >> 10) & 127;
    int b = gidx >> 17;
    int g = lane >> 2, tg = lane & 3;
    int tA = t16 * 16 + g;
    int kA = k16 * 16 + 2 * tg;
    const float* base = feat + ((size_t)b * TT) * DD;
    float2 f00 = *(const float2*)(base + (size_t)tA * DD + kA);
    float2 f10 = *(const float2*)(base + (size_t)(tA + 8) * DD + kA);
    float2 f01 = *(const float2*)(base + (size_t)tA * DD + kA + 8);
    float2 f11 = *(const float2*)(base + (size_t)(tA + 8) * DD + kA + 8);
    uint4 o;
    o.x = pack_h2(f00.x, f00.y);
    o.y = pack_h2(f10.x, f10.y);
    o.z = pack_h2(f01.x, f01.y);
    o.w = pack_h2(f11.x, f11.y);
    g_afrag[gidx] = o;
}

// ---------------- prep: W1 -> fp16 fragment-major (2 n8 per uint4) ----------------
__global__ void prep_bfrag_kernel(const float* __restrict__ W1) {
    int gidx = blockIdx.x * 256 + threadIdx.x;      // 32768
    int lane = gidx & 31;
    int k16 = (gidx >> 5) & 31;
    int n4 = gidx >> 10;
    int g = lane >> 2, tg = lane & 3;
    int k = k16 * 16 + 2 * tg;
    int ua = (2 * n4) * 8 + g;
    int ub = (2 * n4 + 1) * 8 + g;
    uint4 o;
    o.x = pack_h2(W1[(size_t)k * UU + ua],       W1[(size_t)(k + 1) * UU + ua]);
    o.y = pack_h2(W1[(size_t)(k + 8) * UU + ua], W1[(size_t)(k + 9) * UU + ua]);
    o.z = pack_h2(W1[(size_t)k * UU + ub],       W1[(size_t)(k + 1) * UU + ub]);
    o.w = pack_h2(W1[(size_t)(k + 8) * UU + ub], W1[(size_t)(k + 9) * UU + ub]);
    g_bfrag[gidx] = o;
}

// ---------------- comb[b][u] (round-5 version) ----------------
__global__ void comb_kernel(const float* __restrict__ hidden,
                            const float* __restrict__ W2,
                            const float* __restrict__ W1b,
                            const float* __restrict__ W2b) {
    int b = blockIdx.x;
    int u = threadIdx.x;
    __shared__ float h[DD];
    h[u] = hidden[b * DD + u];
    __syncthreads();
    float acc = W1b[u] + W2b[u];
#pragma unroll 8
    for (int d = 0; d < DD; ++d)
        acc = fmaf(h[d], W2[d * UU + u], acc);
    g_comb[b * UU + u] = acc;
}

// ---------------- score GEMM: 8 warps, 64x64 warp tile, deep prefetch cover ----------------
// grid (2 nchunk, 16 ttile, 64 b), 256 threads = 8 warps (2 warpM x 4 warpN)
// warp tile: 64 t-rows (mt 0..3) x 64 u-cols (4 n4 groups); 32 HMMA + 8 LDG.128 per k16
__global__ void __launch_bounds__(256)
score_kernel(const float* __restrict__ Vw) {
    __shared__ float comb_s[256];
    __shared__ float v_s[256];
    __shared__ float srow[128];

    int tid = threadIdx.x;
    int wid = tid >> 5, lane = tid & 31;
    int warpM = wid & 1, warpN = wid >> 1;
    int g = lane >> 2, tg = lane & 3;

    int nchunk = blockIdx.x;
    int t0 = blockIdx.y << 7;
    int b = blockIdx.z;
    int u0 = nchunk << 8;

    if (tid < 256) {
        comb_s[tid] = g_comb[b * UU + u0 + tid];
        v_s[tid] = Vw[u0 + tid];
    }
    if (tid < 128) srow[tid] = 0.f;

    int tt0 = (t0 >> 4) + warpM * 4;     // 4 t16 tiles per warp (mt 0..3)
    const uint4* pA = g_afrag + (((size_t)(b * 128 + tt0) * 32) * 32 + lane);
    const uint4* pB = g_bfrag + (((size_t)(nchunk * 16 + warpN * 4) * 32) * 32 + lane);

    float acc[4][8][4];
#pragma unroll
    for (int i = 0; i < 4; ++i)
#pragma unroll
        for (int j = 0; j < 8; ++j)
#pragma unroll
            for (int q = 0; q < 4; ++q) acc[i][j][q] = 0.f;

    uint4 Ab[2][4], Bb[2][4];
#pragma unroll
    for (int mt = 0; mt < 4; ++mt) Ab[0][mt] = pA[mt * 1024];
#pragma unroll
    for (int j = 0; j < 4; ++j) Bb[0][j] = pB[j * 1024];

#pragma unroll 2
    for (int k16 = 0; k16 < 32; ++k16) {
        int cur = k16 & 1, nxt = cur ^ 1;
        if (k16 < 31) {
            int off = (k16 + 1) * 32;
#pragma unroll
            for (int mt = 0; mt < 4; ++mt) Ab[nxt][mt] = pA[mt * 1024 + off];
#pragma unroll
            for (int j = 0; j < 4; ++j) Bb[nxt][j] = pB[j * 1024 + off];
        }
#pragma unroll
        for (int n4 = 0; n4 < 4; ++n4) {
            uint4 B4 = Bb[cur][n4];
#pragma unroll
            for (int mt = 0; mt < 4; ++mt) {
                mma_f16(acc[mt][2 * n4],     Ab[cur][mt], B4.x, B4.y);
                mma_f16(acc[mt][2 * n4 + 1], Ab[cur][mt], B4.z, B4.w);
            }
        }
    }

    __syncthreads();

    // ---- epilogue: s = sum_u v[u] * tanh(acc + comb[u]) ----
#pragma unroll
    for (int mt = 0; mt < 4; ++mt) {
        float s0 = 0.f, s1 = 0.f;
#pragma unroll
        for (int nt = 0; nt < 8; ++nt) {
#pragma unroll
            for (int j = 0; j < 2; ++j) {
                int ul = warpN * 64 + nt * 8 + 2 * tg + j;
                float cb = comb_s[ul], vv = v_s[ul];
                s0 = fmaf(vv, tanhf(acc[mt][nt][j] + cb), s0);
                s1 = fmaf(vv, tanhf(acc[mt][nt][2 + j] + cb), s1);
            }
        }
        s0 += __shfl_xor_sync(0xffffffffu, s0, 1);
        s0 += __shfl_xor_sync(0xffffffffu, s0, 2);
        s1 += __shfl_xor_sync(0xffffffffu, s1, 1);
        s1 += __shfl_xor_sync(0xffffffffu, s1, 2);
        if (tg == 0) {
            int row = warpM * 64 + mt * 16 + g;
            atomicAdd(&srow[row], s0);
            atomicAdd(&srow[row + 8], s1);
        }
    }
    __syncthreads();
    if (tid < 128)
        g_spart[(size_t)nchunk * BB * TT + b * TT + t0 + tid] = srow[tid];
}

// ---------------- softmax stats + score combine (round-5 version) ----------------
__global__ void stats_kernel() {
    int b = blockIdx.x;
    int tid = threadIdx.x;   // 256
    __shared__ float red[256];
    float m = -INFINITY;
    for (int t = tid; t < TT; t += 256) {
        float sc = g_spart[b * TT + t] + g_spart[BB * TT + b * TT + t];
        g_scores[b * TT + t] = sc;
        m = fmaxf(m, sc);
    }
    red[tid] = m;
    __syncthreads();
    for (int s = 128; s > 0; s >>= 1) {
        if (tid < s) red[tid] = fmaxf(red[tid], red[tid + s]);
        __syncthreads();
    }
    float mx = red[0];
    __syncthreads();
    float sm = 0.f;
    for (int t = tid; t < TT; t += 256)
        sm += expf(g_scores[b * TT + t] - mx);
    red[tid] = sm;
    __syncthreads();
    for (int s = 128; s > 0; s >>= 1) {
        if (tid < s) red[tid] += red[tid + s];
        __syncthreads();
    }
    if (tid == 0) { g_stats[b * 2] = mx; g_stats[b * 2 + 1] = red[0]; }
}

// ---------------- context partials (round-5 version: 16 splits of 128 t) ----------------
__global__ void __launch_bounds__(512)
ctx_partial_kernel(const float* __restrict__ feat) {
    int b = blockIdx.x;
    int s = blockIdx.y;
    int tid = threadIdx.x;
    __shared__ float w[128];
    float mx = g_stats[b * 2], inv = 1.0f / g_stats[b * 2 + 1];
    int t0 = s * 128;
    if (tid < 128)
        w[tid] = expf(g_scores[b * TT + t0 + tid] - mx) * inv;
    __syncthreads();
    int tl = tid >> 7;
    int dq = (tid & 127) << 2;
    float4 acc = make_float4(0.f, 0.f, 0.f, 0.f);
    const float* fb = feat + ((size_t)b * TT + t0) * DD;
#pragma unroll 4
    for (int i = 0; i < 32; ++i) {
        int t = tl + (i << 2);
        float4 f = *(const float4*)(fb + (size_t)t * DD + dq);
        float ww = w[t];
        acc.x = fmaf(ww, f.x, acc.x);
        acc.y = fmaf(ww, f.y, acc.y);
        acc.z = fmaf(ww, f.z, acc.z);
        acc.w = fmaf(ww, f.w, acc.w);
    }
    *(float4*)(&g_partial[((((size_t)b * 16 + s) * 4) + tl) * DD + dq]) = acc;
}

__global__ void ctx_reduce_kernel(float* __restrict__ out) {
    int b = blockIdx.x;
    int d = threadIdx.x;
    float a = 0.f;
#pragma unroll
    for (int s = 0; s < 64; ++s)
        a += g_partial[((size_t)b * 64 + s) * DD + d];
    out[b * DD + d] = a;
}

// ---------------- launch ----------------
extern "C" void kernel_launch(void* const* d_in, const int* in_sizes, int n_in,
                              void* d_out, int out_size) {
    const float* features = (const float*)d_in[0];
    const float* hidden   = (const float*)d_in[1];
    const float* W1_w     = (const float*)d_in[2];
    const float* W1_b     = (const float*)d_in[3];
    const float* W2_w     = (const float*)d_in[4];
    const float* W2_b     = (const float*)d_in[5];
    const float* V_w      = (const float*)d_in[6];
    // V_b: constant shift, softmax-invariant -> dropped
    float* out = (float*)d_out;

    prep_afrag_kernel<<<BB * 128 * 32 * 32 / 256, 256>>>(features);
    prep_bfrag_kernel<<<32 * 32 * 32 / 256, 256>>>(W1_w);
    comb_kernel<<<BB, UU>>>(hidden, W2_w, W1_b, W2_b);

    dim3 sgrid(2, 16, BB);
    score_kernel<<<sgrid, 256>>>(V_w);

    stats_kernel<<<BB, 256>>>();
    dim3 cgrid(BB, 16);
    ctx_partial_kernel<<<cgrid, 512>>>(features);
    ctx_reduce_kernel<<<BB, DD>>>(out);
}